// round 14
// baseline (speedup 1.0000x reference)
#include <cuda_runtime.h>
#include <cstdint>

#define DIM   512
#define NTOK  16384
#define BATCH 8
#define BPB   37                            // blocks per batch; 8*37 = 296 = 148 SMs * occ2
#define TOTAL_BLOCKS (BATCH * BPB)
#define D4    (DIM / 4)

#define STAGES        5
#define TOK_PER_STAGE 8
#define STAGE_BYTES   (TOK_PER_STAGE * DIM * 4)     // 16384
#define RING_BYTES    (STAGES * STAGE_BYTES)        // 81920
#define THREADS       288                           // warp 0 = producer, warps 1..8 = consumers

// Allocation-free scratch (__device__ globals; zero-init at load, self-reset
// each launch -> graph-replay safe).
__device__ float        g_acc[BATCH * DIM];
__device__ float        g_lsum[BATCH];
__device__ unsigned int g_count[BATCH];

// 2048 chunks over 37 blocks: first 13 blocks get 56 chunks, rest get 55.
__device__ __forceinline__ int chunk_start(int idx) {
    return idx * 55 + (idx < 13 ? idx : 13);
}

// ---- mbarrier helpers ----
__device__ __forceinline__ uint32_t smem_u32(const void* p) {
    uint32_t a;
    asm("{ .reg .u64 t; cvta.to.shared.u64 t, %1; cvt.u32.u64 %0, t; }" : "=r"(a) : "l"(p));
    return a;
}
#define MBAR_INIT(addr, cnt) \
    asm volatile("mbarrier.init.shared.b64 [%0], %1;" :: "r"(addr), "r"(cnt) : "memory")
#define MBAR_EXPECT_TX(addr, bytes) \
    asm volatile("mbarrier.arrive.expect_tx.shared.b64 _, [%0], %1;" :: "r"(addr), "r"(bytes) : "memory")
#define MBAR_ARRIVE(addr) \
    asm volatile("mbarrier.arrive.shared.b64 _, [%0];" :: "r"(addr) : "memory")
#define MBAR_WAIT_ACQ(addr, ph) do {                                              \
    asm volatile("{\n\t.reg .pred P;\n\t"                                          \
        "WL_%=:\n\t"                                                               \
        "mbarrier.try_wait.parity.acquire.cta.shared::cta.b64 P, [%0], %1, 0x989680;\n\t" \
        "@P bra WD_%=;\n\t"                                                        \
        "bra WL_%=;\n\t"                                                           \
        "WD_%=:\n\t}" :: "r"(addr), "r"(ph) : "memory");                           \
} while (0)
#define MBAR_WAIT_RLX(addr, ph) do {                                              \
    asm volatile("{\n\t.reg .pred P;\n\t"                                          \
        "WL_%=:\n\t"                                                               \
        "mbarrier.try_wait.parity.relaxed.cta.shared::cta.b64 P, [%0], %1, 0x989680;\n\t" \
        "@P bra WD_%=;\n\t"                                                        \
        "bra WL_%=;\n\t"                                                           \
        "WD_%=:\n\t}" :: "r"(addr), "r"(ph) : "memory");                           \
} while (0)
#define BULK_G2S(dst, src, bytes, mbar)                                            \
    asm volatile("cp.async.bulk.shared::cluster.global.mbarrier::complete_tx::bytes " \
                 "[%0], [%1], %2, [%3];"                                           \
                 :: "r"(dst), "l"(src), "r"(bytes), "r"(mbar) : "memory")

__global__ __launch_bounds__(THREADS, 2)
void ga_fused(const float* __restrict__ x,
              const float* __restrict__ Wa, const float* __restrict__ ba,
              const float* __restrict__ Wg, const float* __restrict__ bg,
              float* __restrict__ out)
{
    extern __shared__ char ring[];                    // 80 KB
    __shared__ __align__(8) unsigned long long mbar[2 * STAGES]; // [2s]=full, [2s+1]=empty
    __shared__ float s_l[8];
    __shared__ unsigned int s_last;

    const int blk = blockIdx.x;
    const int b   = blk / BPB;
    const int idx = blk % BPB;
    const int tid = threadIdx.x;
    const int w   = tid >> 5;
    const int L   = tid & 31;

    const uint32_t ring32 = smem_u32(ring);
    const uint32_t mb32   = smem_u32(mbar);

    if (tid == 0) {
#pragma unroll
        for (int s = 0; s < STAGES; ++s) {
            MBAR_INIT(mb32 + 16u * s,     1u);   // full: completed by TX bytes
            MBAR_INIT(mb32 + 16u * s + 8, 8u);   // empty: 8 consumer-warp arrivals
        }
    }
    __syncthreads();

    const int c0  = chunk_start(idx);
    const int nch = chunk_start(idx + 1) - c0;
    const float* xb = x + (size_t)b * NTOK * DIM;

    float4 acc[4];
#pragma unroll
    for (int j = 0; j < 4; ++j) acc[j] = make_float4(0.f, 0.f, 0.f, 0.f);
    float l = 0.f;

    if (w == 0) {
        // ---- producer: fills EVEN local chunks only (odd go via direct LDG) ----
        int stage = 0, phase = 1;                  // fresh barrier: parity-1 wait passes
        for (int i = 0; i < nch; i += 2) {
            MBAR_WAIT_RLX(mb32 + 16u * stage + 8, phase);
            if (L == 0) {
                MBAR_EXPECT_TX(mb32 + 16u * stage, (unsigned)STAGE_BYTES);
                const float* src = xb + (size_t)(c0 + i) * TOK_PER_STAGE * DIM;
                BULK_G2S(ring32 + stage * STAGE_BYTES, src, (unsigned)STAGE_BYTES,
                         mb32 + 16u * stage);
            }
            if (++stage == STAGES) { stage = 0; phase ^= 1; }
        }
    } else {
        // ---- consumer warps cw=0..7: ring token (even chunk) + direct-LDG token (odd) ----
        const int cw = w - 1;
        const float4* Wa4 = reinterpret_cast<const float4*>(Wa);
        const float4* Wg4 = reinterpret_cast<const float4*>(Wg);
        float4 wa[4], wg[4];
#pragma unroll
        for (int j = 0; j < 4; ++j) { wa[j] = Wa4[j * 32 + L]; wg[j] = Wg4[j * 32 + L]; }
        const float b_a = *ba;
        const float b_g = *bg;

        // One token's register-resident pipeline (identical math to R4).
        auto process = [&](const float4 xv[4]) {
            float da = 0.f, dg = 0.f;
#pragma unroll
            for (int j = 0; j < 4; ++j) {
                da = fmaf(xv[j].x, wa[j].x, da);  da = fmaf(xv[j].y, wa[j].y, da);
                da = fmaf(xv[j].z, wa[j].z, da);  da = fmaf(xv[j].w, wa[j].w, da);
                dg = fmaf(xv[j].x, wg[j].x, dg);  dg = fmaf(xv[j].y, wg[j].y, dg);
                dg = fmaf(xv[j].z, wg[j].z, dg);  dg = fmaf(xv[j].w, wg[j].w, dg);
            }
#pragma unroll
            for (int off = 16; off > 0; off >>= 1) {
                da += __shfl_xor_sync(0xffffffffu, da, off);
                dg += __shfl_xor_sync(0xffffffffu, dg, off);
            }
            const float sa = da + b_a;
            const float sg = dg + b_g;
            const float e2   = __expf(2.f * sa);                 // tanh via exp
            const float attn = (e2 - 1.f) * __frcp_rn(e2 + 1.f);
            const float gate = __frcp_rn(1.f + __expf(-sg));     // sigmoid
            const float p = __expf(attn * gate);  // scores in (-1,1): shift-free softmax safe
            l += p;
#pragma unroll
            for (int j = 0; j < 4; ++j) {
                acc[j].x = fmaf(p, xv[j].x, acc[j].x);
                acc[j].y = fmaf(p, xv[j].y, acc[j].y);
                acc[j].z = fmaf(p, xv[j].z, acc[j].z);
                acc[j].w = fmaf(p, xv[j].w, acc[j].w);
            }
        };

        int stage = 0, phase = 0;
        for (int i = 0; i < nch; i += 2) {
            // Issue direct LDGs for the ODD chunk i+1 BEFORE the barrier wait:
            // their ~600cyc DRAM latency hides under the wait + ring-token compute.
            float4 xd[4];
            const bool have_d = (i + 1 < nch);
            if (have_d) {
                const float4* dp = reinterpret_cast<const float4*>(
                    xb + (size_t)(c0 + i + 1) * TOK_PER_STAGE * DIM) + cw * D4;
#pragma unroll
                for (int j = 0; j < 4; ++j) xd[j] = __ldcs(dp + j * 32 + L);
            }

            // Ring token (even chunk i).
            MBAR_WAIT_ACQ(mb32 + 16u * stage, phase);
            const float4* tok = reinterpret_cast<const float4*>(
                ring + stage * STAGE_BYTES + cw * (DIM * 4));
            float4 xv[4];
#pragma unroll
            for (int j = 0; j < 4; ++j) xv[j] = tok[j * 32 + L];
            process(xv);
            if (L == 0) MBAR_ARRIVE(mb32 + 16u * stage + 8);   // stage consumed
            if (++stage == STAGES) { stage = 0; phase ^= 1; }

            // Direct token (odd chunk i+1) — loads have landed by now.
            if (have_d) process(xd);
        }
    }
    __syncthreads();   // ring is dead -> reuse as combine buffer

    float4* s_acc = reinterpret_cast<float4*>(ring);   // 8 warps * 128 float4 = 16 KB
    if (w >= 1) {
#pragma unroll
        for (int j = 0; j < 4; ++j)
            s_acc[(w - 1) * D4 + j * 32 + L] = acc[j];
        if (L == 0) s_l[w - 1] = l;
    }
    __syncthreads();

    // ---- fold this block's partial into the per-batch gmem accumulator (REDG) ----
    if (tid < D4) {
        float4 s = make_float4(0.f, 0.f, 0.f, 0.f);
#pragma unroll
        for (int ww = 0; ww < 8; ++ww) {
            float4 v = s_acc[ww * D4 + tid];
            s.x += v.x; s.y += v.y; s.z += v.z; s.w += v.w;
        }
        float* dst = &g_acc[b * DIM + 4 * tid];
        atomicAdd(dst + 0, s.x);
        atomicAdd(dst + 1, s.y);
        atomicAdd(dst + 2, s.z);
        atomicAdd(dst + 3, s.w);
    }
    if (tid == 0) {
        float lt = 0.f;
#pragma unroll
        for (int ww = 0; ww < 8; ++ww) lt += s_l[ww];
        atomicAdd(&g_lsum[b], lt);
    }

    // ---- last block of this batch: tiny normalize-and-store finale ----
    __threadfence();
    if (tid == 0) {
        unsigned int old = atomicAdd(&g_count[b], 1u);
        s_last = (old == BPB - 1) ? 1u : 0u;
    }
    __syncthreads();
    if (s_last) {
        __threadfence();
        if (tid == 0) {
            s_l[0] = g_lsum[b];
            g_lsum[b]  = 0.f;   // reset for next graph replay
            g_count[b] = 0;
        }
        __syncthreads();
        const float inv = __frcp_rn(s_l[0]);
        if (tid < D4) {
            float* src = &g_acc[b * DIM + 4 * tid];
            float4 s = make_float4(src[0], src[1], src[2], src[3]);   // L2-hot
            src[0] = 0.f; src[1] = 0.f; src[2] = 0.f; src[3] = 0.f;   // reset for replay
            reinterpret_cast<float4*>(out)[b * D4 + tid] =
                make_float4(s.x * inv, s.y * inv, s.z * inv, s.w * inv);
        }
    }
}

extern "C" void kernel_launch(void* const* d_in, const int* in_sizes, int n_in,
                              void* d_out, int out_size)
{
    const float* x  = (const float*)d_in[0];
    const float* Wa = (const float*)d_in[1];
    const float* ba = (const float*)d_in[2];
    const float* Wg = (const float*)d_in[3];
    const float* bg = (const float*)d_in[4];
    float* out = (float*)d_out;

    cudaFuncSetAttribute(ga_fused, cudaFuncAttributeMaxDynamicSharedMemorySize, RING_BYTES);
    ga_fused<<<TOTAL_BLOCKS, THREADS, RING_BYTES>>>(x, Wa, ba, Wg, bg, out);
}

// round 15
// speedup vs baseline: 1.3046x; 1.3046x over previous
#include <cuda_runtime.h>
#include <cstdint>

#define DIM   512
#define NTOK  16384
#define BATCH 8
#define BPB   37                            // blocks per batch; 8*37 = 296 = 148 SMs * occ2
#define TOTAL_BLOCKS (BATCH * BPB)
#define D4    (DIM / 4)

#define STAGES        5
#define TOK_PER_STAGE 8
#define STAGE_BYTES   (TOK_PER_STAGE * DIM * 4)     // 16384
#define RING_BYTES    (STAGES * STAGE_BYTES)        // 81920
#define THREADS       288                           // warp 0 = producer, warps 1..8 = consumers
#define CHUNKS_PER_BATCH (NTOK / TOK_PER_STAGE)     // 2048

// Allocation-free scratch; fully rewritten every launch (graph-replay safe).
__device__ float4       g_partial_acc[TOTAL_BLOCKS * D4];
__device__ float        g_partial_l[TOTAL_BLOCKS];
__device__ unsigned int g_count[BATCH];   // zero-init; last block resets itself

// 2048 chunks over 37 blocks: first 13 blocks get 56 chunks, rest get 55.
__device__ __forceinline__ int chunk_start(int idx) {
    return idx * 55 + (idx < 13 ? idx : 13);
}

// ---- mbarrier helpers (sm_90+/sm_103a) ----
__device__ __forceinline__ uint32_t smem_u32(const void* p) {
    uint32_t a;
    asm("{ .reg .u64 t; cvta.to.shared.u64 t, %1; cvt.u32.u64 %0, t; }" : "=r"(a) : "l"(p));
    return a;
}
#define MBAR_INIT(addr, cnt) \
    asm volatile("mbarrier.init.shared.b64 [%0], %1;" :: "r"(addr), "r"(cnt) : "memory")
#define MBAR_EXPECT_TX(addr, bytes) \
    asm volatile("mbarrier.arrive.expect_tx.shared.b64 _, [%0], %1;" :: "r"(addr), "r"(bytes) : "memory")
#define MBAR_ARRIVE(addr) \
    asm volatile("mbarrier.arrive.shared.b64 _, [%0];" :: "r"(addr) : "memory")
#define MBAR_WAIT_ACQ(addr, ph) do {                                              \
    asm volatile("{\n\t.reg .pred P;\n\t"                                          \
        "WL_%=:\n\t"                                                               \
        "mbarrier.try_wait.parity.acquire.cta.shared::cta.b64 P, [%0], %1, 0x989680;\n\t" \
        "@P bra WD_%=;\n\t"                                                        \
        "bra WL_%=;\n\t"                                                           \
        "WD_%=:\n\t}" :: "r"(addr), "r"(ph) : "memory");                           \
} while (0)
#define MBAR_WAIT_RLX(addr, ph) do {                                              \
    asm volatile("{\n\t.reg .pred P;\n\t"                                          \
        "WL_%=:\n\t"                                                               \
        "mbarrier.try_wait.parity.relaxed.cta.shared::cta.b64 P, [%0], %1, 0x989680;\n\t" \
        "@P bra WD_%=;\n\t"                                                        \
        "bra WL_%=;\n\t"                                                           \
        "WD_%=:\n\t}" :: "r"(addr), "r"(ph) : "memory");                           \
} while (0)
#define BULK_G2S(dst, src, bytes, mbar)                                            \
    asm volatile("cp.async.bulk.shared::cluster.global.mbarrier::complete_tx::bytes " \
                 "[%0], [%1], %2, [%3];"                                           \
                 :: "r"(dst), "l"(src), "r"(bytes), "r"(mbar) : "memory")

__global__ __launch_bounds__(THREADS, 2)
void ga_fused(const float* __restrict__ x,
              const float* __restrict__ Wa, const float* __restrict__ ba,
              const float* __restrict__ Wg, const float* __restrict__ bg,
              float* __restrict__ out)
{
    extern __shared__ char ring[];                    // 80 KB, 16B-aligned
    __shared__ __align__(8) unsigned long long mbar[2 * STAGES]; // [2s]=full, [2s+1]=empty
    __shared__ float s_l[8];
    __shared__ unsigned int s_last;

    const int blk = blockIdx.x;
    const int b   = blk / BPB;
    const int idx = blk % BPB;
    const int tid = threadIdx.x;
    const int w   = tid >> 5;
    const int L   = tid & 31;

    const uint32_t ring32 = smem_u32(ring);
    const uint32_t mb32   = smem_u32(mbar);

    if (tid == 0) {
#pragma unroll
        for (int s = 0; s < STAGES; ++s) {
            MBAR_INIT(mb32 + 16u * s,     1u);   // full: completed by TX bytes
            MBAR_INIT(mb32 + 16u * s + 8, 8u);   // empty: 8 consumer-warp arrivals
        }
    }
    __syncthreads();

    const int c0  = chunk_start(idx);
    const int nch = chunk_start(idx + 1) - c0;
    const float* xb = x + (size_t)b * NTOK * DIM;

    float4 acc[4];
#pragma unroll
    for (int j = 0; j < 4; ++j) acc[j] = make_float4(0.f, 0.f, 0.f, 0.f);
    float l = 0.f;

    if (w == 0) {
        // ---------------- producer warp ----------------
        int stage = 0, phase = 1;                  // fresh barrier: parity-1 wait passes
        for (int c = 0; c < nch; ++c) {
            MBAR_WAIT_RLX(mb32 + 16u * stage + 8, phase);
            if (L == 0) {
                MBAR_EXPECT_TX(mb32 + 16u * stage, (unsigned)STAGE_BYTES);
                const float* src = xb + (size_t)(c0 + c) * TOK_PER_STAGE * DIM;
                BULK_G2S(ring32 + stage * STAGE_BYTES, src, (unsigned)STAGE_BYTES,
                         mb32 + 16u * stage);
            }
            if (++stage == STAGES) { stage = 0; phase ^= 1; }
        }
    } else {
        // ---------------- consumer warps (cw = 0..7, one token per stage) ----------------
        const int cw = w - 1;
        const float4* Wa4 = reinterpret_cast<const float4*>(Wa);
        const float4* Wg4 = reinterpret_cast<const float4*>(Wg);
        float4 wa[4], wg[4];
#pragma unroll
        for (int j = 0; j < 4; ++j) { wa[j] = Wa4[j * 32 + L]; wg[j] = Wg4[j * 32 + L]; }
        const float b_a = *ba;
        const float b_g = *bg;

        int stage = 0, phase = 0;
        for (int c = 0; c < nch; ++c) {
            MBAR_WAIT_ACQ(mb32 + 16u * stage, phase);
            const float4* tok = reinterpret_cast<const float4*>(
                ring + stage * STAGE_BYTES + cw * (DIM * 4));
            float4 xv[4];
#pragma unroll
            for (int j = 0; j < 4; ++j) xv[j] = tok[j * 32 + L];

            float da = 0.f, dg = 0.f;
#pragma unroll
            for (int j = 0; j < 4; ++j) {
                da = fmaf(xv[j].x, wa[j].x, da);  da = fmaf(xv[j].y, wa[j].y, da);
                da = fmaf(xv[j].z, wa[j].z, da);  da = fmaf(xv[j].w, wa[j].w, da);
                dg = fmaf(xv[j].x, wg[j].x, dg);  dg = fmaf(xv[j].y, wg[j].y, dg);
                dg = fmaf(xv[j].z, wg[j].z, dg);  dg = fmaf(xv[j].w, wg[j].w, dg);
            }
#pragma unroll
            for (int off = 16; off > 0; off >>= 1) {
                da += __shfl_xor_sync(0xffffffffu, da, off);
                dg += __shfl_xor_sync(0xffffffffu, dg, off);
            }
            const float sa = da + b_a;
            const float sg = dg + b_g;
            const float e2   = __expf(2.f * sa);                 // tanh via exp
            const float attn = (e2 - 1.f) * __frcp_rn(e2 + 1.f);
            const float gate = __frcp_rn(1.f + __expf(-sg));     // sigmoid
            const float p = __expf(attn * gate);  // scores in (-1,1): shift-free softmax safe

            l += p;
#pragma unroll
            for (int j = 0; j < 4; ++j) {
                acc[j].x = fmaf(p, xv[j].x, acc[j].x);
                acc[j].y = fmaf(p, xv[j].y, acc[j].y);
                acc[j].z = fmaf(p, xv[j].z, acc[j].z);
                acc[j].w = fmaf(p, xv[j].w, acc[j].w);
            }
            // xv fully consumed above -> safe to release the stage.
            if (L == 0) MBAR_ARRIVE(mb32 + 16u * stage + 8);
            if (++stage == STAGES) { stage = 0; phase ^= 1; }
        }
    }
    __syncthreads();   // all stages consumed; ring is dead -> reuse as combine buffer

    float4* s_acc = reinterpret_cast<float4*>(ring);   // 8 warps * 128 float4 = 16 KB
    if (w >= 1) {
#pragma unroll
        for (int j = 0; j < 4; ++j)
            s_acc[(w - 1) * D4 + j * 32 + L] = acc[j];
        if (L == 0) s_l[w - 1] = l;
    }
    __syncthreads();

    if (tid < D4) {
        float4 s = make_float4(0.f, 0.f, 0.f, 0.f);
#pragma unroll
        for (int ww = 0; ww < 8; ++ww) {
            float4 v = s_acc[ww * D4 + tid];
            s.x += v.x; s.y += v.y; s.z += v.z; s.w += v.w;
        }
        g_partial_acc[blk * D4 + tid] = s;
    }
    if (tid == 0) {
        float lt = 0.f;
#pragma unroll
        for (int ww = 0; ww < 8; ++ww) lt += s_l[ww];
        g_partial_l[blk] = lt;
    }

    // ---- last block of this batch finishes the reduction ----
    __threadfence();
    if (tid == 0) {
        unsigned int old = atomicAdd(&g_count[b], 1u);
        s_last = (old == BPB - 1) ? 1u : 0u;
    }
    __syncthreads();
    if (s_last) {
        if (tid == 0) g_count[b] = 0;   // reset for next graph replay
        if (tid < D4) {
            float4 s = make_float4(0.f, 0.f, 0.f, 0.f);
            float lsum = 0.f;
#pragma unroll
            for (int i = 0; i < BPB; ++i) {
                const int pb = b * BPB + i;
                float4 v = g_partial_acc[pb * D4 + tid];   // L2-hot
                s.x += v.x; s.y += v.y; s.z += v.z; s.w += v.w;
                lsum += g_partial_l[pb];
            }
            const float inv = __frcp_rn(lsum);
            reinterpret_cast<float4*>(out)[b * D4 + tid] =
                make_float4(s.x * inv, s.y * inv, s.z * inv, s.w * inv);
        }
    }
}

extern "C" void kernel_launch(void* const* d_in, const int* in_sizes, int n_in,
                              void* d_out, int out_size)
{
    const float* x  = (const float*)d_in[0];
    const float* Wa = (const float*)d_in[1];
    const float* ba = (const float*)d_in[2];
    const float* Wg = (const float*)d_in[3];
    const float* bg = (const float*)d_in[4];
    float* out = (float*)d_out;

    cudaFuncSetAttribute(ga_fused, cudaFuncAttributeMaxDynamicSharedMemorySize, RING_BYTES);
    ga_fused<<<TOTAL_BLOCKS, THREADS, RING_BYTES>>>(x, Wa, ba, Wg, bg, out);
}